// round 1
// baseline (speedup 1.0000x reference)
#include <cuda_runtime.h>
#include <math.h>

typedef unsigned long long ull;

#define SELU_A 1.6732632423543772f
#define SELU_S 1.0507009873554805f

#define NLINKS_MAX 100000

// ---------------- scratch (no allocations allowed) ----------------
__device__ float g_LS0[NLINKS_MAX * 64];
__device__ float g_LS1[NLINKS_MAX * 64];
__device__ float g_PQ [NLINKS_MAX * 128];
__device__ float g_gemb[256 * 64];
__device__ float g_r1 [256 * 256];
__device__ float g_r2 [256 * 256];

// ---------------- helpers ----------------
__device__ __forceinline__ float selu_f(float x) {
    return x > 0.f ? SELU_S * x : SELU_S * SELU_A * (expf(x) - 1.f);
}
__device__ __forceinline__ ull dup2(float x) {
    ull r; asm("mov.b64 %0, {%1, %1};" : "=l"(r) : "f"(x)); return r;
}
__device__ __forceinline__ void fma2(ull& d, ull a, ull b) {
    asm("fma.rn.f32x2 %0, %1, %2, %0;" : "+l"(d) : "l"(a), "l"(b));
}
__device__ __forceinline__ float lo32(ull v){ return __uint_as_float((unsigned)(v & 0xffffffffull)); }
__device__ __forceinline__ float hi32(ull v){ return __uint_as_float((unsigned)(v >> 32)); }
__device__ __forceinline__ void red4(float* p, float a, float b, float c, float d) {
    asm volatile("red.global.add.v4.f32 [%0], {%1,%2,%3,%4};"
                 :: "l"(p), "f"(a), "f"(b), "f"(c), "f"(d) : "memory");
}

// ============================================================================
// PQ kernel: PQ[i][0:64] = LS[i] @ W_msg[0:64,:], PQ[i][64:128] = LS[i] @ W_msg[64:128,:]
// tile: 64 rows x 128 cols, K=64.  blockDim 128, micro-tile 8x8 (row-paired f32x2).
// dynamic smem: XT[64][68] + W2[64][16*12]  = (4352 + 12288) floats = 66560 B
// ============================================================================
__global__ void __launch_bounds__(128) pq_kernel(const float* __restrict__ LS,
                                                 const float* __restrict__ Wm,
                                                 float* __restrict__ PQ, int N)
{
    extern __shared__ float sm[];
    float* XT = sm;              // [k][row], stride 68
    float* W2 = sm + 64 * 68;    // [k][(j/8)*12 + j%8], stride 192

    int tid  = threadIdx.x;
    int row0 = blockIdx.x * 64;

    // stage W2: thread t owns column j=t for all k
    {
        int j = tid;
        const float* src = (j < 64) ? (Wm + j) : (Wm + 64 * 64 + (j - 64));
        float* dst = W2 + (j >> 3) * 12 + (j & 7);
        #pragma unroll 8
        for (int k = 0; k < 64; ++k)
            dst[k * 192] = src[k * 64];
    }
    // stage XT (transposed LS tile): 2 threads/row
    {
        int r = tid >> 1, h = tid & 1;
        int row = row0 + r;
        const float4* src = (const float4*)(LS + (size_t)row * 64 + h * 32);
        #pragma unroll
        for (int i = 0; i < 8; ++i) {
            float4 v = (row < N) ? src[i] : make_float4(0.f, 0.f, 0.f, 0.f);
            int k = h * 32 + i * 4;
            XT[(k + 0) * 68 + r] = v.x;
            XT[(k + 1) * 68 + r] = v.y;
            XT[(k + 2) * 68 + r] = v.z;
            XT[(k + 3) * 68 + r] = v.w;
        }
    }
    __syncthreads();

    int rg = tid >> 4, cg = tid & 15;
    int r0 = rg * 8, c0 = cg * 8;

    ull acc[4][8];
    #pragma unroll
    for (int p = 0; p < 4; ++p)
        #pragma unroll
        for (int j = 0; j < 8; ++j) acc[p][j] = 0ULL;

    #pragma unroll 4
    for (int k = 0; k < 64; ++k) {
        const ull* aP = (const ull*)(XT + k * 68 + r0);
        ull a[4]; a[0]=aP[0]; a[1]=aP[1]; a[2]=aP[2]; a[3]=aP[3];
        const float4* wp = (const float4*)(W2 + k * 192 + cg * 12);
        float4 w0 = wp[0], w1 = wp[1];
        ull b[8];
        b[0]=dup2(w0.x); b[1]=dup2(w0.y); b[2]=dup2(w0.z); b[3]=dup2(w0.w);
        b[4]=dup2(w1.x); b[5]=dup2(w1.y); b[6]=dup2(w1.z); b[7]=dup2(w1.w);
        #pragma unroll
        for (int j = 0; j < 8; ++j) {
            fma2(acc[0][j], a[0], b[j]);
            fma2(acc[1][j], a[1], b[j]);
            fma2(acc[2][j], a[2], b[j]);
            fma2(acc[3][j], a[3], b[j]);
        }
    }

    #pragma unroll
    for (int p = 0; p < 4; ++p) {
        int rlo = row0 + r0 + 2 * p;
        int rhi = rlo + 1;
        if (rlo < N) {
            float4 v0 = make_float4(lo32(acc[p][0]), lo32(acc[p][1]), lo32(acc[p][2]), lo32(acc[p][3]));
            float4 v1 = make_float4(lo32(acc[p][4]), lo32(acc[p][5]), lo32(acc[p][6]), lo32(acc[p][7]));
            *(float4*)(PQ + (size_t)rlo * 128 + c0)     = v0;
            *(float4*)(PQ + (size_t)rlo * 128 + c0 + 4) = v1;
        }
        if (rhi < N) {
            float4 v0 = make_float4(hi32(acc[p][0]), hi32(acc[p][1]), hi32(acc[p][2]), hi32(acc[p][3]));
            float4 v1 = make_float4(hi32(acc[p][4]), hi32(acc[p][5]), hi32(acc[p][6]), hi32(acc[p][7]));
            *(float4*)(PQ + (size_t)rhi * 128 + c0)     = v0;
            *(float4*)(PQ + (size_t)rhi * 128 + c0 + 4) = v1;
        }
    }
}

// ============================================================================
// Edge kernel: for 128 edges: msg = selu(P[first]+Q[second]+b_msg);
// h = relu(msg @ W_gcn + b_gcn); red-add h into NS[second].
// blockDim 128, micro-tile 8 edges x 8 cols (edge-paired f32x2).
// dynamic smem: MsgT[64][132] + WgS[64][8*12] + sbg[64] + sbm[64]
//             = (8448 + 6144 + 128) floats = 58880 B
// ============================================================================
__global__ void __launch_bounds__(128) edge_kernel(const float* __restrict__ PQ,
                                                   const int*   __restrict__ first,
                                                   const int*   __restrict__ second,
                                                   const float* __restrict__ bmsg,
                                                   const float* __restrict__ Wg,
                                                   const float* __restrict__ bgcn,
                                                   float* __restrict__ NS, int E)
{
    extern __shared__ float sm[];
    float* MsgT = sm;                 // [k][edge], stride 132
    float* WgS  = sm + 64 * 132;      // [k][(j/8)*12 + j%8], stride 96
    float* sbg  = WgS + 64 * 96;
    float* sbm  = sbg + 64;

    int tid = threadIdx.x;
    long eb = (long)blockIdx.x * 128;

    if (tid < 64) { sbg[tid] = bgcn[tid]; sbm[tid] = bmsg[tid]; }

    // stage W_gcn (padded layout, conflict-free GEMM reads)
    {
        int j = tid & 63, kh = tid >> 6;                  // kh = 0/1 -> k halves
        const float* src = Wg + kh * 32 * 64 + j;
        float* dst = WgS + kh * 32 * 96 + (j >> 3) * 12 + (j & 7);
        #pragma unroll 8
        for (int i = 0; i < 32; ++i)
            dst[i * 96] = src[i * 64];
    }
    __syncthreads();   // sbm ready

    // stage msg (one edge per thread), transposed into MsgT[k][e]
    {
        long e = eb + tid;
        bool valid = e < E;
        int f = valid ? first[e]  : 0;
        int s = valid ? second[e] : 0;
        const float4* Pp = (const float4*)(PQ + (size_t)f * 128);
        const float4* Qp = (const float4*)(PQ + (size_t)s * 128 + 64);
        #pragma unroll
        for (int i = 0; i < 16; ++i) {
            float4 p = Pp[i], q = Qp[i];
            int k = i * 4;
            float m0 = valid ? selu_f(p.x + q.x + sbm[k + 0]) : 0.f;
            float m1 = valid ? selu_f(p.y + q.y + sbm[k + 1]) : 0.f;
            float m2 = valid ? selu_f(p.z + q.z + sbm[k + 2]) : 0.f;
            float m3 = valid ? selu_f(p.w + q.w + sbm[k + 3]) : 0.f;
            MsgT[(k + 0) * 132 + tid] = m0;
            MsgT[(k + 1) * 132 + tid] = m1;
            MsgT[(k + 2) * 132 + tid] = m2;
            MsgT[(k + 3) * 132 + tid] = m3;
        }
    }
    __syncthreads();

    int rg = tid >> 3, cg = tid & 7;
    int r0 = rg * 8, c0 = cg * 8;

    ull acc[4][8];
    #pragma unroll
    for (int p = 0; p < 4; ++p)
        #pragma unroll
        for (int j = 0; j < 8; ++j) acc[p][j] = 0ULL;

    #pragma unroll 4
    for (int k = 0; k < 64; ++k) {
        const ull* aP = (const ull*)(MsgT + k * 132 + r0);
        ull a[4]; a[0]=aP[0]; a[1]=aP[1]; a[2]=aP[2]; a[3]=aP[3];
        const float4* wp = (const float4*)(WgS + k * 96 + cg * 12);
        float4 w0 = wp[0], w1 = wp[1];
        ull b[8];
        b[0]=dup2(w0.x); b[1]=dup2(w0.y); b[2]=dup2(w0.z); b[3]=dup2(w0.w);
        b[4]=dup2(w1.x); b[5]=dup2(w1.y); b[6]=dup2(w1.z); b[7]=dup2(w1.w);
        #pragma unroll
        for (int j = 0; j < 8; ++j) {
            fma2(acc[0][j], a[0], b[j]);
            fma2(acc[1][j], a[1], b[j]);
            fma2(acc[2][j], a[2], b[j]);
            fma2(acc[3][j], a[3], b[j]);
        }
    }

    // epilogue: bias + relu + vectorized scatter-add
    #pragma unroll
    for (int p = 0; p < 4; ++p) {
        long elo = eb + r0 + 2 * p;
        long ehi = elo + 1;
        if (elo < E) {
            int dd = second[elo];
            float* base = NS + (size_t)dd * 64 + c0;
            red4(base,
                 fmaxf(lo32(acc[p][0]) + sbg[c0 + 0], 0.f),
                 fmaxf(lo32(acc[p][1]) + sbg[c0 + 1], 0.f),
                 fmaxf(lo32(acc[p][2]) + sbg[c0 + 2], 0.f),
                 fmaxf(lo32(acc[p][3]) + sbg[c0 + 3], 0.f));
            red4(base + 4,
                 fmaxf(lo32(acc[p][4]) + sbg[c0 + 4], 0.f),
                 fmaxf(lo32(acc[p][5]) + sbg[c0 + 5], 0.f),
                 fmaxf(lo32(acc[p][6]) + sbg[c0 + 6], 0.f),
                 fmaxf(lo32(acc[p][7]) + sbg[c0 + 7], 0.f));
        }
        if (ehi < E) {
            int dd = second[ehi];
            float* base = NS + (size_t)dd * 64 + c0;
            red4(base,
                 fmaxf(hi32(acc[p][0]) + sbg[c0 + 0], 0.f),
                 fmaxf(hi32(acc[p][1]) + sbg[c0 + 1], 0.f),
                 fmaxf(hi32(acc[p][2]) + sbg[c0 + 2], 0.f),
                 fmaxf(hi32(acc[p][3]) + sbg[c0 + 3], 0.f));
            red4(base + 4,
                 fmaxf(hi32(acc[p][4]) + sbg[c0 + 4], 0.f),
                 fmaxf(hi32(acc[p][5]) + sbg[c0 + 5], 0.f),
                 fmaxf(hi32(acc[p][6]) + sbg[c0 + 6], 0.f),
                 fmaxf(hi32(acc[p][7]) + sbg[c0 + 7], 0.f));
        }
    }
}

// ============================================================================
// Readout
// ============================================================================
__device__ __forceinline__ int lower_bound_i(const int* a, int n, int v) {
    int lo = 0, hi = n;
    while (lo < hi) { int m = (lo + hi) >> 1; if (a[m] < v) lo = m + 1; else hi = m; }
    return lo;
}

__global__ void gemb_kernel(const float* __restrict__ LS, const int* __restrict__ gid,
                            float* __restrict__ gemb, int N)
{
    int g = blockIdx.x, c = threadIdx.x;   // 64 threads
    int lo = lower_bound_i(gid, N, g);
    int hi = lower_bound_i(gid, N, g + 1);
    float s = 0.f;
    for (int i = lo; i < hi; ++i) s += LS[(size_t)i * 64 + c];
    gemb[g * 64 + c] = s;
}

__global__ void r1_kernel(const float* __restrict__ ge, const float* __restrict__ W,
                          const float* __restrict__ b, float* __restrict__ out)
{
    __shared__ float xs[64];
    int g = blockIdx.x, j = threadIdx.x;   // 256 threads
    if (j < 64) xs[j] = ge[g * 64 + j];
    __syncthreads();
    float acc = b[j];
    #pragma unroll 8
    for (int k = 0; k < 64; ++k) acc += xs[k] * W[k * 256 + j];
    out[g * 256 + j] = selu_f(acc);
}

__global__ void r2_kernel(const float* __restrict__ r1, const float* __restrict__ W,
                          const float* __restrict__ b, float* __restrict__ out)
{
    __shared__ float xs[256];
    int g = blockIdx.x, j = threadIdx.x;   // 256 threads
    xs[j] = r1[g * 256 + j];
    __syncthreads();
    float acc = b[j];
    #pragma unroll 8
    for (int k = 0; k < 256; ++k) acc += xs[k] * W[k * 256 + j];
    out[g * 256 + j] = selu_f(acc);
}

__global__ void r3_kernel(const float* __restrict__ r2, const float* __restrict__ W,
                          const float* __restrict__ b, float* __restrict__ out)
{
    __shared__ float red[8];
    int g = blockIdx.x, t = threadIdx.x;   // 256 threads
    float v = r2[g * 256 + t] * W[t];
    #pragma unroll
    for (int o = 16; o > 0; o >>= 1) v += __shfl_down_sync(0xffffffffu, v, o);
    if ((t & 31) == 0) red[t >> 5] = v;
    __syncthreads();
    if (t == 0) {
        float s = 0.f;
        #pragma unroll
        for (int i = 0; i < 8; ++i) s += red[i];
        out[g] = s + b[0];
    }
}

// ============================================================================
// Launch
// ============================================================================
extern "C" void kernel_launch(void* const* d_in, const int* in_sizes, int n_in,
                              void* d_out, int out_size)
{
    const float* x    = (const float*)d_in[0];
    const float* Wm   = (const float*)d_in[1];
    const float* bm   = (const float*)d_in[2];
    const float* Wg   = (const float*)d_in[3];
    const float* bg   = (const float*)d_in[4];
    const float* Wr1  = (const float*)d_in[5];
    const float* br1  = (const float*)d_in[6];
    const float* Wr2  = (const float*)d_in[7];
    const float* br2  = (const float*)d_in[8];
    const float* Wr3  = (const float*)d_in[9];
    const float* br3  = (const float*)d_in[10];
    const int*   gid  = (const int*)d_in[11];
    const int*   fst  = (const int*)d_in[12];
    const int*   snd  = (const int*)d_in[13];

    int N = in_sizes[0] / 64;
    int E = in_sizes[12];
    int G = out_size;

    float *ls0, *ls1, *pq, *ge, *r1b, *r2b;
    cudaGetSymbolAddress((void**)&ls0, g_LS0);
    cudaGetSymbolAddress((void**)&ls1, g_LS1);
    cudaGetSymbolAddress((void**)&pq,  g_PQ);
    cudaGetSymbolAddress((void**)&ge,  g_gemb);
    cudaGetSymbolAddress((void**)&r1b, g_r1);
    cudaGetSymbolAddress((void**)&r2b, g_r2);

    const int SMEM_PQ   = (64 * 68 + 64 * 192) * 4;          // 66560 B
    const int SMEM_EDGE = (64 * 132 + 64 * 96 + 128) * 4;    // 58880 B
    cudaFuncSetAttribute(pq_kernel,   cudaFuncAttributeMaxDynamicSharedMemorySize, SMEM_PQ);
    cudaFuncSetAttribute(edge_kernel, cudaFuncAttributeMaxDynamicSharedMemorySize, SMEM_EDGE);

    const float* src = x;
    float* bufs[2] = { ls0, ls1 };
    for (int t = 0; t < 4; ++t) {
        pq_kernel<<<(N + 63) / 64, 128, SMEM_PQ>>>(src, Wm, pq, N);
        float* dst = bufs[t & 1];
        cudaMemsetAsync(dst, 0, (size_t)N * 64 * sizeof(float));
        edge_kernel<<<(E + 127) / 128, 128, SMEM_EDGE>>>(pq, fst, snd, bm, Wg, bg, dst, E);
        src = dst;
    }

    gemb_kernel<<<G, 64>>>(src, gid, ge, N);
    r1_kernel<<<G, 256>>>(ge, Wr1, br1, r1b);
    r2_kernel<<<G, 256>>>(r1b, Wr2, br2, r2b);
    r3_kernel<<<G, 256>>>(r2b, Wr3, br3, (float*)d_out);
}